// round 5
// baseline (speedup 1.0000x reference)
#include <cuda_runtime.h>
#include <stdint.h>

#define N_TOKENS 131072
#define D_MODEL  512
#define PATHS    16
#define CAP      16384                 // 2 * N / P
#define D4       (D_MODEL / 4)         // 128 float4 per row
#define ROWS     (PATHS * CAP)         // 262144 output rows

#define SMS      148
#define BPSM     3
#define GRID     (SMS * BPSM)          // 444 blocks, all co-resident
#define TPB      512                   // 16 warps
#define NWARP    16

#define NB_R     256                   // route blocks (bid < NB_R do routing)
#define TOK_PER_BLK 512                // NB_R * 512 = 131072

#define AGGF    0x40000000u
#define PREFIXF 0x80000000u
#define VALM    0x00FFFFFFu

// ---- scratch (no allocations allowed; zero-initialized at load) ----
__device__ int      g_cnt[PATHS];          // per-path count, clamped to CAP
__device__ int      g_slot[ROWS];          // slot -> token gather map
__device__ unsigned g_desc[NB_R * PATHS];  // decoupled-lookback descriptors
__device__ unsigned g_bar0;                // grid barrier (route -> gather)
__device__ unsigned g_bar1;                // exit counter (self-clean)

__device__ __forceinline__ unsigned vload(const unsigned* p) {
    return *(volatile const unsigned*)p;
}

__global__ __launch_bounds__(TPB, BPSM) void k_fused(const float* __restrict__ score,
                                                     const float4* __restrict__ in4,
                                                     float4* __restrict__ out4) {
    __shared__ uint8_t sh_pid[TOK_PER_BLK];
    __shared__ int sh_cnt[NWARP][PATHS];
    __shared__ int sh_wexcl[NWARP][PATHS];
    __shared__ int sh_agg[PATHS];
    __shared__ int sh_excl[PATHS];
    __shared__ int sh_run[NWARP][PATHS];
    __shared__ int sh_last;
    const int tid = threadIdx.x, w = tid >> 5, lane = tid & 31, bid = blockIdx.x;

    // ================= ROUTE PHASE (blocks 0..NB_R-1) =================
    if (bid < NB_R) {
        const int blk0 = bid * TOK_PER_BLK;
        const int li = w * 32 + lane;                 // one token per thread

        // argmax + per-warp per-path counts
        if (lane < PATHS) sh_cnt[w][lane] = 0;
        __syncwarp();
        {
            const float4* sc = (const float4*)(score + (size_t)(blk0 + li) * PATHS);
            float4 a = __ldcs(sc), b = __ldcs(sc + 1), c = __ldcs(sc + 2), d = __ldcs(sc + 3);
            float v[16] = {a.x,a.y,a.z,a.w, b.x,b.y,b.z,b.w,
                           c.x,c.y,c.z,c.w, d.x,d.y,d.z,d.w};
            int best = 0; float bv = v[0];
            #pragma unroll
            for (int p = 1; p < 16; p++) if (v[p] > bv) { bv = v[p]; best = p; }  // first-max
            sh_pid[li] = (uint8_t)best;
            unsigned m = __match_any_sync(0xffffffffu, best);
            if ((__ffs(m) - 1) == lane) sh_cnt[w][best] += __popc(m);
        }
        __syncthreads();

        // block-local scan over 16 warps + aggregate publish
        if (w == 0 && lane < PATHS) {
            int run = 0;
            #pragma unroll
            for (int ww = 0; ww < NWARP; ww++) { int v = sh_cnt[ww][lane]; sh_wexcl[ww][lane] = run; run += v; }
            sh_agg[lane] = run;
            unsigned pub = (bid == 0) ? ((unsigned)run | PREFIXF) : ((unsigned)run | AGGF);
            atomicExch(&g_desc[bid * PATHS + lane], pub);
        }
        __syncthreads();

        // decoupled lookback: warp w owns path w
        {
            const int p = w;
            int excl = 0;
            if (bid > 0) {
                int j = bid - 1;
                while (true) {
                    const int idx = j - lane;              // lane 0 = nearest predecessor
                    unsigned v = (idx >= 0) ? vload(&g_desc[idx * PATHS + p]) : PREFIXF;
                    unsigned bP = __ballot_sync(0xffffffffu, (v & PREFIXF) != 0);
                    unsigned bN = __ballot_sync(0xffffffffu, (v & (PREFIXF | AGGF)) == 0);
                    int fP = bP ? (__ffs(bP) - 1) : 32;
                    int fN = bN ? (__ffs(bN) - 1) : 32;
                    if (fP < fN) {                         // prefix found before any gap
                        int add = (lane <= fP) ? (int)(v & VALM) : 0;
                        excl += __reduce_add_sync(0xffffffffu, add);
                        break;
                    } else {                               // consume ready AGGs (fN may be 32)
                        int add = (lane < fN) ? (int)(v & VALM) : 0;
                        excl += __reduce_add_sync(0xffffffffu, add);
                        j -= fN;                           // fN==0 -> spin on same window
                    }
                }
                if (lane == 0)
                    atomicExch(&g_desc[bid * PATHS + p], (unsigned)(excl + sh_agg[p]) | PREFIXF);
            }
            if (lane == 0) {
                sh_excl[p] = excl;
                if (bid == NB_R - 1) { int tot = excl + sh_agg[p]; g_cnt[p] = tot < CAP ? tot : CAP; }
            }
        }
        __syncthreads();

        // order-preserving rank -> slot map
        if (lane < PATHS) sh_run[w][lane] = sh_excl[lane] + sh_wexcl[w][lane];
        __syncwarp();
        {
            const int p = (int)sh_pid[li];
            unsigned m = __match_any_sync(0xffffffffu, p);
            const int rank = __popc(m & ((1u << lane) - 1u));
            const int pos = sh_run[w][p] + rank;
            if (pos < CAP) g_slot[p * CAP + pos] = blk0 + li;
        }
    }

    // ================= GRID BARRIER =================
    __syncthreads();
    if (tid == 0) {
        __threadfence();
        atomicAdd(&g_bar0, 1u);
        while (vload(&g_bar0) < (unsigned)GRID) { }
    }
    __syncthreads();
    __threadfence();

    // ================= GATHER PHASE (grid-stride, MLP=4 per row) =================
    const int gw = bid * NWARP + w;                    // global warp id, 0..GRID*16-1
    for (int r = gw; r < ROWS; r += GRID * NWARP) {
        const int p = r >> 14;                         // r / CAP
        const int j = r & (CAP - 1);                   // r % CAP
        float4 v0 = make_float4(0.f,0.f,0.f,0.f);
        float4 v1 = v0, v2 = v0, v3 = v0;
        if (j < g_cnt[p]) {
            const float4* src = in4 + (size_t)g_slot[r] * D4 + lane;
            v0 = __ldcs(src);
            v1 = __ldcs(src + 32);
            v2 = __ldcs(src + 64);
            v3 = __ldcs(src + 96);
        }
        float4* dst = out4 + (size_t)r * D4 + lane;
        __stcs(dst,      v0);
        __stcs(dst + 32, v1);
        __stcs(dst + 64, v2);
        __stcs(dst + 96, v3);
    }

    // ================= SELF-CLEAN (deterministic graph replay) =================
    __syncthreads();
    if (tid == 0) sh_last = (atomicAdd(&g_bar1, 1u) == (unsigned)(GRID - 1));
    __syncthreads();
    if (sh_last) {
        for (int i = tid; i < NB_R * PATHS; i += TPB) g_desc[i] = 0;
        if (tid == 0) { g_bar0 = 0; g_bar1 = 0; }
    }
}

extern "C" void kernel_launch(void* const* d_in, const int* in_sizes, int n_in,
                              void* d_out, int out_size) {
    const float* inputs = (const float*)d_in[0];
    const float* score  = (const float*)d_in[1];
    if (in_sizes[0] == N_TOKENS * PATHS) {   // defensive: identify by element count
        inputs = (const float*)d_in[1];
        score  = (const float*)d_in[0];
    }
    k_fused<<<GRID, TPB>>>(score, (const float4*)inputs, (float4*)d_out);
}

// round 6
// speedup vs baseline: 1.1836x; 1.1836x over previous
#include <cuda_runtime.h>
#include <stdint.h>

#define N_TOKENS 131072
#define D_MODEL  512
#define PATHS    16
#define CAP      16384                 // 2 * N / P
#define D4       (D_MODEL / 4)         // 128 float4 per row

#define NB       256                   // route blocks (all co-resident: 512thr, <=4/SM)
#define TPB      512                   // 16 warps, one token per thread
#define NWARP    16

// ---- scratch (no allocations allowed; zero-initialized at load) ----
__device__ int      g_cnt[PATHS];          // per-path count, clamped to CAP
__device__ int      g_slot[PATHS * CAP];   // slot -> token gather map
__device__ int      g_hist[PATHS * NB];    // per-(path, block) counts  [path][block]
__device__ unsigned g_arrive;              // grid barrier counter (self-resets)
__device__ unsigned g_done;                // completion counter (self-resets)

__device__ __forceinline__ unsigned vload(const unsigned* p) {
    return *(volatile const unsigned*)p;
}

// Route: argmax + per-warp hist + block scan -> publish hist -> resident-grid
// barrier -> each warp bulk-reads its path's hist row and computes its block's
// exclusive prefix -> order-preserving positions -> slot map. One launch.
__global__ __launch_bounds__(TPB, 4) void k_route(const float* __restrict__ score) {
    __shared__ int sh_cnt[NWARP][PATHS];
    __shared__ int sh_wexcl[NWARP][PATHS];
    __shared__ int sh_excl[PATHS];
    __shared__ int sh_run[NWARP][PATHS];
    __shared__ int sh_last;
    const int tid = threadIdx.x, w = tid >> 5, lane = tid & 31, bid = blockIdx.x;
    const int tok = bid * TPB + tid;                    // one token per thread

    // ---- phase 1: argmax + per-warp per-path counts ----
    if (lane < PATHS) sh_cnt[w][lane] = 0;
    __syncwarp();
    int best;
    {
        const float4* sc = (const float4*)(score + (size_t)tok * PATHS);
        float4 a = __ldcs(sc), b = __ldcs(sc + 1), c = __ldcs(sc + 2), d = __ldcs(sc + 3);
        float v[16] = {a.x,a.y,a.z,a.w, b.x,b.y,b.z,b.w,
                       c.x,c.y,c.z,c.w, d.x,d.y,d.z,d.w};
        best = 0; float bv = v[0];
        #pragma unroll
        for (int p = 1; p < 16; p++) if (v[p] > bv) { bv = v[p]; best = p; }  // first-max
        unsigned m = __match_any_sync(0xffffffffu, best);
        if ((__ffs(m) - 1) == lane) sh_cnt[w][best] += __popc(m);
    }
    __syncthreads();

    // ---- block scan over 16 warps + publish block aggregate ----
    if (w == 0 && lane < PATHS) {
        int run = 0;
        #pragma unroll
        for (int ww = 0; ww < NWARP; ww++) { int v = sh_cnt[ww][lane]; sh_wexcl[ww][lane] = run; run += v; }
        g_hist[lane * NB + bid] = run;                  // [path][block], coalesced read later
    }
    __syncthreads();

    // ---- resident-grid barrier (all NB blocks co-resident by construction) ----
    if (tid == 0) {
        __threadfence();
        atomicAdd(&g_arrive, 1u);
        while (vload(&g_arrive) < (unsigned)NB) { }
    }
    __syncthreads();
    __threadfence();
#if __CUDA_ARCH__ >= 900
    cudaTriggerProgrammaticLaunchCompletion();          // let gather begin launching
#endif

    // ---- bulk prefix: warp w owns path w; read full hist row from L2 ----
    {
        int excl = 0, tot = 0;
        #pragma unroll
        for (int s = 0; s < NB / 32; s++) {
            const int j = s * 32 + lane;
            const int v = g_hist[w * NB + j];
            tot += v;
            if (j < bid) excl += v;
        }
        excl = __reduce_add_sync(0xffffffffu, excl);
        tot  = __reduce_add_sync(0xffffffffu, tot);
        if (lane == 0) {
            sh_excl[w] = excl;
            if (bid == 0) g_cnt[w] = tot < CAP ? tot : CAP;
        }
    }
    __syncthreads();

    // ---- order-preserving rank -> slot map ----
    if (lane < PATHS) sh_run[w][lane] = sh_excl[lane] + sh_wexcl[w][lane];
    __syncwarp();
    {
        unsigned m = __match_any_sync(0xffffffffu, best);
        const int rank = __popc(m & ((1u << lane) - 1u));
        const int pos = sh_run[w][best] + rank;
        if (pos < CAP) g_slot[best * CAP + pos] = tok;
    }

    // ---- self-clean for deterministic graph replay ----
    __syncthreads();
    if (tid == 0) sh_last = (atomicAdd(&g_done, 1u) == (unsigned)(NB - 1));
    __syncthreads();
    if (sh_last && tid == 0) { g_arrive = 0; g_done = 0; }
}

// Gather: one warp per output row, 4 independent float4s per lane (MLP=4).
#define GROWS_PB 16
__global__ __launch_bounds__(512) void k_gather(const float4* __restrict__ in4,
                                                float4* __restrict__ out4) {
#if __CUDA_ARCH__ >= 900
    cudaGridDependencySynchronize();                    // PDL: wait for k_route results
#endif
    const int w = threadIdx.x >> 5, lane = threadIdx.x & 31;
    const int r = blockIdx.x * GROWS_PB + w;            // output row in [0, P*CAP)
    const int p = r >> 14;                              // r / CAP
    const int j = r & (CAP - 1);                        // r % CAP
    float4 v0 = make_float4(0.f,0.f,0.f,0.f);
    float4 v1 = v0, v2 = v0, v3 = v0;
    if (j < g_cnt[p]) {
        const float4* src = in4 + (size_t)g_slot[r] * D4 + lane;
        v0 = __ldcs(src);
        v1 = __ldcs(src + 32);
        v2 = __ldcs(src + 64);
        v3 = __ldcs(src + 96);
    }
    float4* dst = out4 + (size_t)r * D4 + lane;
    __stcs(dst,      v0);
    __stcs(dst + 32, v1);
    __stcs(dst + 64, v2);
    __stcs(dst + 96, v3);
}

extern "C" void kernel_launch(void* const* d_in, const int* in_sizes, int n_in,
                              void* d_out, int out_size) {
    const float* inputs = (const float*)d_in[0];
    const float* score  = (const float*)d_in[1];
    if (in_sizes[0] == N_TOKENS * PATHS) {   // defensive: identify by element count
        inputs = (const float*)d_in[1];
        score  = (const float*)d_in[0];
    }
    k_route<<<NB, TPB>>>(score);

    cudaLaunchConfig_t cfg = {};
    cfg.gridDim  = dim3((PATHS * CAP) / GROWS_PB, 1, 1);
    cfg.blockDim = dim3(512, 1, 1);
    cfg.stream   = 0;
    cudaLaunchAttribute attr[1];
    attr[0].id = cudaLaunchAttributeProgrammaticStreamSerialization;
    attr[0].val.programmaticStreamSerializationAllowed = 1;
    cfg.attrs = attr;
    cfg.numAttrs = 1;
    cudaLaunchKernelEx(&cfg, k_gather, (const float4*)inputs, (float4*)d_out);
}

// round 7
// speedup vs baseline: 1.1839x; 1.0002x over previous
#include <cuda_runtime.h>
#include <stdint.h>

#define N_TOKENS 131072
#define D_MODEL  512
#define PATHS    16
#define CAP      16384                 // 2 * N / P
#define D4       (D_MODEL / 4)         // 128 float4 per row

#define NB       256                   // route blocks (all co-resident: 512thr, <=4/SM)
#define TPB      512                   // 16 warps, one token per thread
#define NWARP    16

// ---- scratch (no allocations allowed; zero-initialized at load) ----
__device__ int      g_cnt[PATHS];          // per-path count, clamped to CAP
__device__ int      g_slot[PATHS * CAP];   // slot -> token gather map
__device__ int      g_hist[PATHS * NB];    // per-(path, block) counts  [path][block]
__device__ unsigned g_arrive;              // grid barrier counter (self-resets)
__device__ unsigned g_done;                // completion counter (self-resets)

__device__ __forceinline__ unsigned vload(const unsigned* p) {
    return *(volatile const unsigned*)p;
}

// Route: argmax + per-warp hist + block scan -> publish hist -> resident-grid
// barrier -> each warp bulk-reads its path's hist row and computes its block's
// exclusive prefix -> order-preserving positions -> slot map. One launch.
__global__ __launch_bounds__(TPB, 4) void k_route(const float* __restrict__ score) {
#if __CUDA_ARCH__ >= 900
    // Fire immediately: lets the (huge) gather grid be scheduled and parked in
    // cudaGridDependencySynchronize while route runs. gridDepSync still waits
    // for this grid's FULL completion, so no ordering hazard.
    cudaTriggerProgrammaticLaunchCompletion();
#endif
    __shared__ int sh_cnt[NWARP][PATHS];
    __shared__ int sh_wexcl[NWARP][PATHS];
    __shared__ int sh_excl[PATHS];
    __shared__ int sh_run[NWARP][PATHS];
    __shared__ int sh_last;
    const int tid = threadIdx.x, w = tid >> 5, lane = tid & 31, bid = blockIdx.x;
    const int tok = bid * TPB + tid;                    // one token per thread

    // ---- phase 1: argmax + per-warp per-path counts ----
    if (lane < PATHS) sh_cnt[w][lane] = 0;
    __syncwarp();
    int best;
    {
        const float4* sc = (const float4*)(score + (size_t)tok * PATHS);
        float4 a = __ldcs(sc), b = __ldcs(sc + 1), c = __ldcs(sc + 2), d = __ldcs(sc + 3);
        float v[16] = {a.x,a.y,a.z,a.w, b.x,b.y,b.z,b.w,
                       c.x,c.y,c.z,c.w, d.x,d.y,d.z,d.w};
        best = 0; float bv = v[0];
        #pragma unroll
        for (int p = 1; p < 16; p++) if (v[p] > bv) { bv = v[p]; best = p; }  // first-max
        unsigned m = __match_any_sync(0xffffffffu, best);
        if ((__ffs(m) - 1) == lane) sh_cnt[w][best] += __popc(m);
    }
    __syncthreads();

    // ---- block scan over 16 warps + publish block aggregate ----
    if (w == 0 && lane < PATHS) {
        int run = 0;
        #pragma unroll
        for (int ww = 0; ww < NWARP; ww++) { int v = sh_cnt[ww][lane]; sh_wexcl[ww][lane] = run; run += v; }
        g_hist[lane * NB + bid] = run;                  // [path][block], coalesced read later
    }
    __syncthreads();

    // ---- resident-grid barrier (all NB blocks co-resident by construction) ----
    if (tid == 0) {
        __threadfence();
        atomicAdd(&g_arrive, 1u);
        while (vload(&g_arrive) < (unsigned)NB) { }
    }
    __syncthreads();
    __threadfence();

    // ---- bulk prefix: warp w owns path w; read full hist row from L2 ----
    {
        int excl = 0, tot = 0;
        #pragma unroll
        for (int s = 0; s < NB / 32; s++) {
            const int j = s * 32 + lane;
            const int v = g_hist[w * NB + j];
            tot += v;
            if (j < bid) excl += v;
        }
        excl = __reduce_add_sync(0xffffffffu, excl);
        tot  = __reduce_add_sync(0xffffffffu, tot);
        if (lane == 0) {
            sh_excl[w] = excl;
            if (bid == 0) g_cnt[w] = tot < CAP ? tot : CAP;
        }
    }
    __syncthreads();

    // ---- order-preserving rank -> slot map ----
    if (lane < PATHS) sh_run[w][lane] = sh_excl[lane] + sh_wexcl[w][lane];
    __syncwarp();
    {
        unsigned m = __match_any_sync(0xffffffffu, best);
        const int rank = __popc(m & ((1u << lane) - 1u));
        const int pos = sh_run[w][best] + rank;
        if (pos < CAP) g_slot[best * CAP + pos] = tok;
    }

    // ---- self-clean for deterministic graph replay ----
    __syncthreads();
    if (tid == 0) sh_last = (atomicAdd(&g_done, 1u) == (unsigned)(NB - 1));
    __syncthreads();
    if (sh_last && tid == 0) { g_arrive = 0; g_done = 0; }
}

// Gather: one warp per output row, 4 independent float4s per lane (MLP=4).
#define GROWS_PB 16
__global__ __launch_bounds__(512) void k_gather(const float4* __restrict__ in4,
                                                float4* __restrict__ out4) {
#if __CUDA_ARCH__ >= 900
    cudaGridDependencySynchronize();                    // PDL: wait for k_route results
#endif
    const int w = threadIdx.x >> 5, lane = threadIdx.x & 31;
    const int r = blockIdx.x * GROWS_PB + w;            // output row in [0, P*CAP)
    const int p = r >> 14;                              // r / CAP
    const int j = r & (CAP - 1);                        // r % CAP
    float4 v0 = make_float4(0.f,0.f,0.f,0.f);
    float4 v1 = v0, v2 = v0, v3 = v0;
    if (j < g_cnt[p]) {
        const float4* src = in4 + (size_t)g_slot[r] * D4 + lane;
        v0 = src[0];
        v1 = src[32];
        v2 = src[64];
        v3 = src[96];
    }
    float4* dst = out4 + (size_t)r * D4 + lane;
    dst[0]  = v0;
    dst[32] = v1;
    dst[64] = v2;
    dst[96] = v3;
}

extern "C" void kernel_launch(void* const* d_in, const int* in_sizes, int n_in,
                              void* d_out, int out_size) {
    const float* inputs = (const float*)d_in[0];
    const float* score  = (const float*)d_in[1];
    if (in_sizes[0] == N_TOKENS * PATHS) {   // defensive: identify by element count
        inputs = (const float*)d_in[1];
        score  = (const float*)d_in[0];
    }
    k_route<<<NB, TPB>>>(score);

    cudaLaunchConfig_t cfg = {};
    cfg.gridDim  = dim3((PATHS * CAP) / GROWS_PB, 1, 1);
    cfg.blockDim = dim3(512, 1, 1);
    cfg.stream   = 0;
    cudaLaunchAttribute attr[1];
    attr[0].id = cudaLaunchAttributeProgrammaticStreamSerialization;
    attr[0].val.programmaticStreamSerializationAllowed = 1;
    cfg.attrs = attr;
    cfg.numAttrs = 1;
    cudaLaunchKernelEx(&cfg, k_gather, (const float4*)inputs, (float4*)d_out);
}